// round 15
// baseline (speedup 1.0000x reference)
#include <cuda_runtime.h>
#include <cstddef>
#include <cstdint>

// Problem constants
#define B_   4
#define TQ_  512
#define TP_  512
#define D_   256

// ---------------------------------------------------------------------------
// Scratch (static device globals)
// ---------------------------------------------------------------------------
__device__ float g_sc[(size_t)B_ * TP_ * TQ_];   // exp(scores) [B,Tp,Tq]
__device__ float g_cpart[B_ * 8 * TQ_];          // per-p-tile column partials
// Shared split-K partial buffer: proj uses 4 slices of B*TQ*D (8MB);
// out uses 32 slices of TP*D (16MB).  Serial kernels -> safe reuse.
__device__ float g_part[(size_t)32 * TP_ * D_];

// ---------------------------------------------------------------------------
// fp32 HW tanh (1 MUFU op).
// ---------------------------------------------------------------------------
__device__ __forceinline__ float ftanh(float x) {
    float r;
    asm("tanh.approx.f32 %0, %1;" : "=f"(r) : "f"(x));
    return r;
}

__device__ __forceinline__ uint32_t f2tf32(float x) {
    uint32_t r;
    asm("cvt.rna.tf32.f32 %0, %1;" : "=r"(r) : "f"(x));
    return r;
}

// ---------------------------------------------------------------------------
// tf32 tensor-core GEMM slice.  Block tile 64x128, BK=32, single-buffered,
// 256 threads = 8 warps (2m x 4n), warp tile 32x32 (8 MMAs / 16 LDS).
// C[M,N] (partial) = A[M, kbeg:kend] * B[kbeg:kend, N], both row-major.
// If SCALE, A column k is scaled by cs[k] at load (cs may be smem).
// ---------------------------------------------------------------------------
template <bool SCALE>
__device__ __forceinline__ void tf32_gemm_64x128(const float* __restrict__ A,
                                                 const float* __restrict__ B,
                                                 float* __restrict__ C,
                                                 const float* cs,
                                                 int N, int K, int kbeg, int kend,
                                                 int m0, int n0) {
    __shared__ uint32_t As[64][36];   // [m][k]
    __shared__ uint32_t Bs[32][136];  // [k][n]

    const int tid = threadIdx.x;
    const int lane = tid & 31;
    const int w = tid >> 5;
    const int wm = (w >> 2) * 32;   // 0 / 32
    const int wn = (w & 3) * 32;    // 0 / 32 / 64 / 96
    const int frow = lane >> 2;     // 0..7
    const int fcol = lane & 3;      // 0..3

    float c[2][4][4];
#pragma unroll
    for (int mi = 0; mi < 2; mi++)
#pragma unroll
        for (int ni = 0; ni < 4; ni++)
#pragma unroll
            for (int k = 0; k < 4; k++) c[mi][ni][k] = 0.0f;

    float4 ra[2], rb[4];
    auto loadG = [&](int k0) {
#pragma unroll
        for (int s = 0; s < 2; s++) {
            int id = tid + s * 256;
            int r = id >> 3, cc = (id & 7) * 4;
            ra[s] = *(const float4*)&A[(size_t)(m0 + r) * K + k0 + cc];
            if (SCALE) {
                float4 sc = *(const float4*)&cs[k0 + cc];
                ra[s].x *= sc.x; ra[s].y *= sc.y;
                ra[s].z *= sc.z; ra[s].w *= sc.w;
            }
        }
#pragma unroll
        for (int s = 0; s < 4; s++) {
            int id = tid + s * 256;
            int r = id >> 5, cc = (id & 31) * 4;
            rb[s] = *(const float4*)&B[(size_t)(k0 + r) * N + n0 + cc];
        }
    };
    auto storeS = [&]() {
#pragma unroll
        for (int s = 0; s < 2; s++) {
            int id = tid + s * 256;
            int r = id >> 3, cc = (id & 7) * 4;
            As[r][cc + 0] = f2tf32(ra[s].x);
            As[r][cc + 1] = f2tf32(ra[s].y);
            As[r][cc + 2] = f2tf32(ra[s].z);
            As[r][cc + 3] = f2tf32(ra[s].w);
        }
#pragma unroll
        for (int s = 0; s < 4; s++) {
            int id = tid + s * 256;
            int r = id >> 5, cc = (id & 31) * 4;
            Bs[r][cc + 0] = f2tf32(rb[s].x);
            Bs[r][cc + 1] = f2tf32(rb[s].y);
            Bs[r][cc + 2] = f2tf32(rb[s].z);
            Bs[r][cc + 3] = f2tf32(rb[s].w);
        }
    };

    loadG(kbeg);
    for (int k0 = kbeg; k0 < kend; k0 += 32) {
        storeS();
        __syncthreads();
        if (k0 + 32 < kend) loadG(k0 + 32);
#pragma unroll
        for (int ks = 0; ks < 4; ks++) {
            const int kk = ks * 8;
            uint32_t a[2][4], bfr[4][2];
#pragma unroll
            for (int mi = 0; mi < 2; mi++) {
                a[mi][0] = As[wm + mi * 16 + frow][kk + fcol];
                a[mi][1] = As[wm + mi * 16 + frow + 8][kk + fcol];
                a[mi][2] = As[wm + mi * 16 + frow][kk + fcol + 4];
                a[mi][3] = As[wm + mi * 16 + frow + 8][kk + fcol + 4];
            }
#pragma unroll
            for (int ni = 0; ni < 4; ni++) {
                bfr[ni][0] = Bs[kk + fcol][wn + ni * 8 + frow];
                bfr[ni][1] = Bs[kk + fcol + 4][wn + ni * 8 + frow];
            }
#pragma unroll
            for (int mi = 0; mi < 2; mi++)
#pragma unroll
                for (int ni = 0; ni < 4; ni++)
                    asm volatile(
                        "mma.sync.aligned.m16n8k8.row.col.f32.tf32.tf32.f32 "
                        "{%0,%1,%2,%3},{%4,%5,%6,%7},{%8,%9},{%0,%1,%2,%3};"
                        : "+f"(c[mi][ni][0]), "+f"(c[mi][ni][1]),
                          "+f"(c[mi][ni][2]), "+f"(c[mi][ni][3])
                        : "r"(a[mi][0]), "r"(a[mi][1]), "r"(a[mi][2]),
                          "r"(a[mi][3]), "r"(bfr[ni][0]), "r"(bfr[ni][1]));
        }
        __syncthreads();
    }

#pragma unroll
    for (int mi = 0; mi < 2; mi++)
#pragma unroll
        for (int ni = 0; ni < 4; ni++) {
            int rr = m0 + wm + mi * 16 + frow;
            int cc = n0 + wn + ni * 8 + fcol * 2;
            *(float2*)&C[(size_t)rr * N + cc] =
                make_float2(c[mi][ni][0], c[mi][ni][1]);
            *(float2*)&C[(size_t)(rr + 8) * N + cc] =
                make_float2(c[mi][ni][2], c[mi][ni][3]);
        }
}

// ---------------------------------------------------------------------------
// Kernel 1: projections (tf32 TC), split-K=2.  z = t + 2*s.
//   part[s*2+t] = (t?p:q)[:, ks:ks+128] @ (t?W1:W0)[ks:ks+128, :]
// grid (2, 32, 4) = 256 blocks.  NO reduce kernel -- energy sums the two
// split partials inline (hidden under its double-buffered MUFU loop).
// ---------------------------------------------------------------------------
__global__ __launch_bounds__(256) void proj_kernel(const float* __restrict__ q,
                                                   const float* __restrict__ p,
                                                   const float* __restrict__ W0,
                                                   const float* __restrict__ W1) {
    const int t = blockIdx.z & 1;
    const int s = blockIdx.z >> 1;
    const float* A = t ? p : q;
    const float* Bw = t ? W1 : W0;
    float* C = g_part + (size_t)(s * 2 + t) * (B_ * TQ_ * D_);
    tf32_gemm_64x128<false>(A, Bw, C, nullptr, D_, D_,
                            s * 128, s * 128 + 128,
                            blockIdx.y * 64, blockIdx.x * 128);
}

// ---------------------------------------------------------------------------
// Kernel 2: energies -> exp(score) + per-block column partial sums.
// fp32 MUFU.TANH, 64x64 tile, 4x4 micro -- AT the MUFU floor.
// DOUBLE-BUFFERED: chunk k+1's 16 LDG.128 (both proj split partials for pp
// and pq) issue before chunk k's MUFU loop; the partial sum a+b happens in
// storeS afterwards, so the extra loads hide under ~14K cyc of MUFU work.
// ---------------------------------------------------------------------------
__global__ __launch_bounds__(256) void energy_kernel(const float* __restrict__ vc) {
    __shared__ float sp[2][64][33];
    __shared__ float sq[2][64][33];
    __shared__ float sv[256];
    __shared__ float colred[16][64];

    const int b = blockIdx.z;
    const int p0 = blockIdx.y * 64;
    const int q0 = blockIdx.x * 64;
    const int tid = threadIdx.x;
    const int tx = tid & 15;
    const int ty = tid >> 4;

    constexpr size_t NFT = (size_t)B_ * TQ_ * D_;
    // proj slices: t=0 -> pq, t=1 -> pp; split s=0 slices {0,1}, s=1 {2,3}
    const float* pq0 = g_part + 0 * NFT + ((size_t)b * TQ_ + q0) * D_;
    const float* pq1 = g_part + 2 * NFT + ((size_t)b * TQ_ + q0) * D_;
    const float* pp0 = g_part + 1 * NFT + ((size_t)b * TP_ + p0) * D_;
    const float* pp1 = g_part + 3 * NFT + ((size_t)b * TP_ + p0) * D_;

    sv[tid] = vc[tid];

    float4 rPa[2], rPb[2], rQa[2], rQb[2];
    auto loadG = [&](int d0) {
#pragma unroll
        for (int s = 0; s < 2; s++) {
            int id = tid + s * 256;
            int r = id >> 3, cc = (id & 7) * 4;
            size_t off = (size_t)r * D_ + d0 + cc;
            rPa[s] = *(const float4*)&pp0[off];
            rPb[s] = *(const float4*)&pp1[off];
            rQa[s] = *(const float4*)&pq0[off];
            rQb[s] = *(const float4*)&pq1[off];
        }
    };
    auto storeS = [&](int st) {
#pragma unroll
        for (int s = 0; s < 2; s++) {
            int id = tid + s * 256;
            int r = id >> 3, cc = (id & 7) * 4;
            sp[st][r][cc + 0] = rPa[s].x + rPb[s].x;
            sp[st][r][cc + 1] = rPa[s].y + rPb[s].y;
            sp[st][r][cc + 2] = rPa[s].z + rPb[s].z;
            sp[st][r][cc + 3] = rPa[s].w + rPb[s].w;
            sq[st][r][cc + 0] = rQa[s].x + rQb[s].x;
            sq[st][r][cc + 1] = rQa[s].y + rQb[s].y;
            sq[st][r][cc + 2] = rQa[s].z + rQb[s].z;
            sq[st][r][cc + 3] = rQa[s].w + rQb[s].w;
        }
    };

    float acc[4][4];
#pragma unroll
    for (int i = 0; i < 4; i++)
#pragma unroll
        for (int j = 0; j < 4; j++) acc[i][j] = 0.0f;

    loadG(0);
    storeS(0);
    __syncthreads();

#pragma unroll 1
    for (int ch = 0; ch < 8; ch++) {
        if (ch < 7) loadG((ch + 1) * 32);
        const int st = ch & 1;
#pragma unroll 8
        for (int d = 0; d < 32; d++) {
            float v = sv[ch * 32 + d];
            float a[4], bb[4];
#pragma unroll
            for (int i = 0; i < 4; i++) a[i] = sp[st][ty * 4 + i][d];
#pragma unroll
            for (int j = 0; j < 4; j++) bb[j] = sq[st][tx * 4 + j][d];
#pragma unroll
            for (int i = 0; i < 4; i++)
#pragma unroll
                for (int j = 0; j < 4; j++)
                    acc[i][j] = fmaf(v, ftanh(a[i] + bb[j]), acc[i][j]);
        }
        if (ch < 7) storeS((ch + 1) & 1);
        __syncthreads();
    }

    float colp[4] = {0.f, 0.f, 0.f, 0.f};
#pragma unroll
    for (int i = 0; i < 4; i++) {
        float4 o;
        o.x = __expf(acc[i][0]);
        o.y = __expf(acc[i][1]);
        o.z = __expf(acc[i][2]);
        o.w = __expf(acc[i][3]);
        colp[0] += o.x; colp[1] += o.y; colp[2] += o.z; colp[3] += o.w;
        *(float4*)&g_sc[((size_t)b * TP_ + p0 + ty * 4 + i) * TQ_ + q0 + tx * 4] = o;
    }
    *(float4*)&colred[ty][tx * 4] =
        make_float4(colp[0], colp[1], colp[2], colp[3]);
    __syncthreads();
    if (tid < 64) {
        float s = colred[0][tid];
#pragma unroll
        for (int t = 1; t < 16; t++) s += colred[t][tid];
        g_cpart[(b * 8 + blockIdx.y) * TQ_ + q0 + tid] = s;
    }
}

// ---------------------------------------------------------------------------
// Kernel 3: out GEMM (tf32 TC), split-K=8 (grid 512 -> ~2 blocks/SM under
// the 2-block reg cap), in-block column-sum inverse + normalize fused into
// A load.  z = b + 4*s.  grid (2, 8, 32) = 512 blocks.
// ---------------------------------------------------------------------------
__global__ __launch_bounds__(256) void out_gemm_kernel(const float* __restrict__ qin) {
    __shared__ __align__(16) float sinv[64];

    const int b = blockIdx.z & 3;
    const int s = blockIdx.z >> 2;
    const int kbeg = s * 64;
    const int tid = threadIdx.x;

    if (tid < 64) {
        const int qq = kbeg + tid;
        float sum = 0.f;
#pragma unroll
        for (int t = 0; t < 8; t++) sum += g_cpart[(b * 8 + t) * TQ_ + qq];
        sinv[tid] = __fdividef(1.0f, sum);
    }
    __syncthreads();

    float* C = g_part + (size_t)(s * 4 + b) * (TP_ * D_);
    tf32_gemm_64x128<true>(g_sc + (size_t)b * TP_ * TQ_,
                           qin + (size_t)b * TQ_ * D_, C,
                           sinv - kbeg, D_, TQ_,
                           kbeg, kbeg + 64,
                           blockIdx.y * 64, blockIdx.x * 128);
}

// Reduce out partials: out = sum over 8 splits in fixed order.  Deterministic.
__global__ __launch_bounds__(256) void out_reduce_kernel(float* __restrict__ out) {
    const int i = blockIdx.x * 256 + threadIdx.x;  // float4 idx
    constexpr int NB4 = (TP_ * D_) / 4;
    const int b = i / NB4;
    const int j = i % NB4;
    float4 v[8];
#pragma unroll
    for (int s = 0; s < 8; s++)
        v[s] = *((const float4*)g_part + (size_t)(s * 4 + b) * NB4 + j);
    float4 r;
    r.x = ((v[0].x + v[1].x) + (v[2].x + v[3].x)) +
          ((v[4].x + v[5].x) + (v[6].x + v[7].x));
    r.y = ((v[0].y + v[1].y) + (v[2].y + v[3].y)) +
          ((v[4].y + v[5].y) + (v[6].y + v[7].y));
    r.z = ((v[0].z + v[1].z) + (v[2].z + v[3].z)) +
          ((v[4].z + v[5].z) + (v[6].z + v[7].z));
    r.w = ((v[0].w + v[1].w) + (v[2].w + v[3].w)) +
          ((v[4].w + v[5].w) + (v[6].w + v[7].w));
    *((float4*)out + i) = r;
}

// ---------------------------------------------------------------------------
// Launch.  Measured dead ends: multi-stream per-batch pipelining +4us;
// inline dual-partial reads in SINGLE-buffered energy +12us (retrying now
// under double-buffering); 128x64/BK=16 double-buffered gemm tile +4us;
// fused last-block reduces (threadfence) +7us; f16x2 tanh 2-pass on MUFU.
// ---------------------------------------------------------------------------
extern "C" void kernel_launch(void* const* d_in, const int* in_sizes, int n_in,
                              void* d_out, int out_size) {
    const float* q = (const float*)d_in[0];   // [B,Tq,D]
    const float* p = (const float*)d_in[1];   // [B,Tp,D]
    const float* W0 = (const float*)d_in[2];  // [D,D]
    const float* W1 = (const float*)d_in[3];  // [D,D]
    const float* vc = (const float*)d_in[4];  // [D,1]
    float* out = (float*)d_out;               // [B,Tp,D]

    // 1. Projections (tensor core, split-K=2; partials consumed by energy)
    {
        dim3 grid(D_ / 128, (B_ * TQ_) / 64, 4);
        proj_kernel<<<grid, 256>>>(q, p, W0, W1);
    }
    // 2. Energies -> exp(score) + column partials (inline proj reduce,
    //    double-buffered)
    {
        dim3 grid(TQ_ / 64, TP_ / 64, B_);
        energy_kernel<<<grid, 256>>>(vc);
    }
    // 3. Output GEMM (tensor core, split-K=8, in-block colsum + normalize)
    {
        dim3 grid(D_ / 128, TP_ / 64, 32);
        out_gemm_kernel<<<grid, 256>>>(q);
        out_reduce_kernel<<<(B_ * TP_ * D_ / 4) / 256, 256>>>(out);
    }
}

// round 16
// speedup vs baseline: 1.0189x; 1.0189x over previous
#include <cuda_runtime.h>
#include <cstddef>
#include <cstdint>

// Problem constants
#define B_   4
#define TQ_  512
#define TP_  512
#define D_   256

// ---------------------------------------------------------------------------
// Scratch (static device globals)
// ---------------------------------------------------------------------------
__device__ float g_sc[(size_t)B_ * TP_ * TQ_];   // exp(scores) [B,Tp,Tq]
__device__ float g_cpart[B_ * 8 * TQ_];          // per-p-tile column partials
// Shared split-K partial buffer: proj uses 4 slices of B*TQ*D (8MB);
// out uses 16 slices of TP*D (8MB).  Serial kernels -> safe reuse.
__device__ float g_part[(size_t)16 * B_ * TQ_ * D_ / 4];

// ---------------------------------------------------------------------------
// fp32 HW tanh (1 MUFU op).
// ---------------------------------------------------------------------------
__device__ __forceinline__ float ftanh(float x) {
    float r;
    asm("tanh.approx.f32 %0, %1;" : "=f"(r) : "f"(x));
    return r;
}

__device__ __forceinline__ uint32_t f2tf32(float x) {
    uint32_t r;
    asm("cvt.rna.tf32.f32 %0, %1;" : "=r"(r) : "f"(x));
    return r;
}

// ---------------------------------------------------------------------------
// tf32 tensor-core GEMM slice.  Block tile 64x128, BK=32, single-buffered,
// 256 threads = 8 warps (2m x 4n), warp tile 32x32 (8 MMAs / 16 LDS).
// C[M,N] (partial) = A[M, kbeg:kend] * B[kbeg:kend, N], both row-major.
// If SCALE, A column k is scaled by cs[k] at load (cs may be smem).
// ---------------------------------------------------------------------------
template <bool SCALE>
__device__ __forceinline__ void tf32_gemm_64x128(const float* __restrict__ A,
                                                 const float* __restrict__ B,
                                                 float* __restrict__ C,
                                                 const float* cs,
                                                 int N, int K, int kbeg, int kend,
                                                 int m0, int n0) {
    __shared__ uint32_t As[64][36];   // [m][k]
    __shared__ uint32_t Bs[32][136];  // [k][n]

    const int tid = threadIdx.x;
    const int lane = tid & 31;
    const int w = tid >> 5;
    const int wm = (w >> 2) * 32;   // 0 / 32
    const int wn = (w & 3) * 32;    // 0 / 32 / 64 / 96
    const int frow = lane >> 2;     // 0..7
    const int fcol = lane & 3;      // 0..3

    float c[2][4][4];
#pragma unroll
    for (int mi = 0; mi < 2; mi++)
#pragma unroll
        for (int ni = 0; ni < 4; ni++)
#pragma unroll
            for (int k = 0; k < 4; k++) c[mi][ni][k] = 0.0f;

    float4 ra[2], rb[4];
    auto loadG = [&](int k0) {
#pragma unroll
        for (int s = 0; s < 2; s++) {
            int id = tid + s * 256;
            int r = id >> 3, cc = (id & 7) * 4;
            ra[s] = *(const float4*)&A[(size_t)(m0 + r) * K + k0 + cc];
            if (SCALE) {
                float4 sc = *(const float4*)&cs[k0 + cc];
                ra[s].x *= sc.x; ra[s].y *= sc.y;
                ra[s].z *= sc.z; ra[s].w *= sc.w;
            }
        }
#pragma unroll
        for (int s = 0; s < 4; s++) {
            int id = tid + s * 256;
            int r = id >> 5, cc = (id & 31) * 4;
            rb[s] = *(const float4*)&B[(size_t)(k0 + r) * N + n0 + cc];
        }
    };
    auto storeS = [&]() {
#pragma unroll
        for (int s = 0; s < 2; s++) {
            int id = tid + s * 256;
            int r = id >> 3, cc = (id & 7) * 4;
            As[r][cc + 0] = f2tf32(ra[s].x);
            As[r][cc + 1] = f2tf32(ra[s].y);
            As[r][cc + 2] = f2tf32(ra[s].z);
            As[r][cc + 3] = f2tf32(ra[s].w);
        }
#pragma unroll
        for (int s = 0; s < 4; s++) {
            int id = tid + s * 256;
            int r = id >> 5, cc = (id & 31) * 4;
            Bs[r][cc + 0] = f2tf32(rb[s].x);
            Bs[r][cc + 1] = f2tf32(rb[s].y);
            Bs[r][cc + 2] = f2tf32(rb[s].z);
            Bs[r][cc + 3] = f2tf32(rb[s].w);
        }
    };

    loadG(kbeg);
    for (int k0 = kbeg; k0 < kend; k0 += 32) {
        storeS();
        __syncthreads();
        if (k0 + 32 < kend) loadG(k0 + 32);
#pragma unroll
        for (int ks = 0; ks < 4; ks++) {
            const int kk = ks * 8;
            uint32_t a[2][4], bfr[4][2];
#pragma unroll
            for (int mi = 0; mi < 2; mi++) {
                a[mi][0] = As[wm + mi * 16 + frow][kk + fcol];
                a[mi][1] = As[wm + mi * 16 + frow + 8][kk + fcol];
                a[mi][2] = As[wm + mi * 16 + frow][kk + fcol + 4];
                a[mi][3] = As[wm + mi * 16 + frow + 8][kk + fcol + 4];
            }
#pragma unroll
            for (int ni = 0; ni < 4; ni++) {
                bfr[ni][0] = Bs[kk + fcol][wn + ni * 8 + frow];
                bfr[ni][1] = Bs[kk + fcol + 4][wn + ni * 8 + frow];
            }
#pragma unroll
            for (int mi = 0; mi < 2; mi++)
#pragma unroll
                for (int ni = 0; ni < 4; ni++)
                    asm volatile(
                        "mma.sync.aligned.m16n8k8.row.col.f32.tf32.tf32.f32 "
                        "{%0,%1,%2,%3},{%4,%5,%6,%7},{%8,%9},{%0,%1,%2,%3};"
                        : "+f"(c[mi][ni][0]), "+f"(c[mi][ni][1]),
                          "+f"(c[mi][ni][2]), "+f"(c[mi][ni][3])
                        : "r"(a[mi][0]), "r"(a[mi][1]), "r"(a[mi][2]),
                          "r"(a[mi][3]), "r"(bfr[ni][0]), "r"(bfr[ni][1]));
        }
        __syncthreads();
    }

#pragma unroll
    for (int mi = 0; mi < 2; mi++)
#pragma unroll
        for (int ni = 0; ni < 4; ni++) {
            int rr = m0 + wm + mi * 16 + frow;
            int cc = n0 + wn + ni * 8 + fcol * 2;
            *(float2*)&C[(size_t)rr * N + cc] =
                make_float2(c[mi][ni][0], c[mi][ni][1]);
            *(float2*)&C[(size_t)(rr + 8) * N + cc] =
                make_float2(c[mi][ni][2], c[mi][ni][3]);
        }
}

// ---------------------------------------------------------------------------
// Kernel 1: projections (tf32 TC), split-K=2.  z = t + 2*s.
//   part[s*2+t] = (t?p:q)[:, ks:ks+128] @ (t?W1:W0)[ks:ks+128, :]
// grid (2, 32, 4) = 256 blocks.  NO reduce kernel -- energy sums the two
// split partials inline (hidden under its double-buffered MUFU loop).
// ---------------------------------------------------------------------------
__global__ __launch_bounds__(256) void proj_kernel(const float* __restrict__ q,
                                                   const float* __restrict__ p,
                                                   const float* __restrict__ W0,
                                                   const float* __restrict__ W1) {
    const int t = blockIdx.z & 1;
    const int s = blockIdx.z >> 1;
    const float* A = t ? p : q;
    const float* Bw = t ? W1 : W0;
    float* C = g_part + (size_t)(s * 2 + t) * (B_ * TQ_ * D_);
    tf32_gemm_64x128<false>(A, Bw, C, nullptr, D_, D_,
                            s * 128, s * 128 + 128,
                            blockIdx.y * 64, blockIdx.x * 128);
}

// ---------------------------------------------------------------------------
// Kernel 2: energies -> exp(score) + per-block column partial sums.
// fp32 MUFU.TANH, 64x64 tile, 4x4 micro -- AT the MUFU floor.
// DOUBLE-BUFFERED: chunk k+1's 16 LDG.128 (both proj split partials for pp
// and pq) issue before chunk k's MUFU loop; the partial sum a+b happens in
// storeS afterwards, so the extra loads hide under ~14K cyc of MUFU work.
// ---------------------------------------------------------------------------
__global__ __launch_bounds__(256) void energy_kernel(const float* __restrict__ vc) {
    __shared__ float sp[2][64][33];
    __shared__ float sq[2][64][33];
    __shared__ float sv[256];
    __shared__ float colred[16][64];

    const int b = blockIdx.z;
    const int p0 = blockIdx.y * 64;
    const int q0 = blockIdx.x * 64;
    const int tid = threadIdx.x;
    const int tx = tid & 15;
    const int ty = tid >> 4;

    constexpr size_t NFT = (size_t)B_ * TQ_ * D_;
    // proj slices: t=0 -> pq, t=1 -> pp; split s=0 slices {0,1}, s=1 {2,3}
    const float* pq0 = g_part + 0 * NFT + ((size_t)b * TQ_ + q0) * D_;
    const float* pq1 = g_part + 2 * NFT + ((size_t)b * TQ_ + q0) * D_;
    const float* pp0 = g_part + 1 * NFT + ((size_t)b * TP_ + p0) * D_;
    const float* pp1 = g_part + 3 * NFT + ((size_t)b * TP_ + p0) * D_;

    sv[tid] = vc[tid];

    float4 rPa[2], rPb[2], rQa[2], rQb[2];
    auto loadG = [&](int d0) {
#pragma unroll
        for (int s = 0; s < 2; s++) {
            int id = tid + s * 256;
            int r = id >> 3, cc = (id & 7) * 4;
            size_t off = (size_t)r * D_ + d0 + cc;
            rPa[s] = *(const float4*)&pp0[off];
            rPb[s] = *(const float4*)&pp1[off];
            rQa[s] = *(const float4*)&pq0[off];
            rQb[s] = *(const float4*)&pq1[off];
        }
    };
    auto storeS = [&](int st) {
#pragma unroll
        for (int s = 0; s < 2; s++) {
            int id = tid + s * 256;
            int r = id >> 3, cc = (id & 7) * 4;
            sp[st][r][cc + 0] = rPa[s].x + rPb[s].x;
            sp[st][r][cc + 1] = rPa[s].y + rPb[s].y;
            sp[st][r][cc + 2] = rPa[s].z + rPb[s].z;
            sp[st][r][cc + 3] = rPa[s].w + rPb[s].w;
            sq[st][r][cc + 0] = rQa[s].x + rQb[s].x;
            sq[st][r][cc + 1] = rQa[s].y + rQb[s].y;
            sq[st][r][cc + 2] = rQa[s].z + rQb[s].z;
            sq[st][r][cc + 3] = rQa[s].w + rQb[s].w;
        }
    };

    float acc[4][4];
#pragma unroll
    for (int i = 0; i < 4; i++)
#pragma unroll
        for (int j = 0; j < 4; j++) acc[i][j] = 0.0f;

    loadG(0);
    storeS(0);
    __syncthreads();

#pragma unroll 1
    for (int ch = 0; ch < 8; ch++) {
        if (ch < 7) loadG((ch + 1) * 32);
        const int st = ch & 1;
#pragma unroll 8
        for (int d = 0; d < 32; d++) {
            float v = sv[ch * 32 + d];
            float a[4], bb[4];
#pragma unroll
            for (int i = 0; i < 4; i++) a[i] = sp[st][ty * 4 + i][d];
#pragma unroll
            for (int j = 0; j < 4; j++) bb[j] = sq[st][tx * 4 + j][d];
#pragma unroll
            for (int i = 0; i < 4; i++)
#pragma unroll
                for (int j = 0; j < 4; j++)
                    acc[i][j] = fmaf(v, ftanh(a[i] + bb[j]), acc[i][j]);
        }
        if (ch < 7) storeS((ch + 1) & 1);
        __syncthreads();
    }

    float colp[4] = {0.f, 0.f, 0.f, 0.f};
#pragma unroll
    for (int i = 0; i < 4; i++) {
        float4 o;
        o.x = __expf(acc[i][0]);
        o.y = __expf(acc[i][1]);
        o.z = __expf(acc[i][2]);
        o.w = __expf(acc[i][3]);
        colp[0] += o.x; colp[1] += o.y; colp[2] += o.z; colp[3] += o.w;
        *(float4*)&g_sc[((size_t)b * TP_ + p0 + ty * 4 + i) * TQ_ + q0 + tx * 4] = o;
    }
    *(float4*)&colred[ty][tx * 4] =
        make_float4(colp[0], colp[1], colp[2], colp[3]);
    __syncthreads();
    if (tid < 64) {
        float s = colred[0][tid];
#pragma unroll
        for (int t = 1; t < 16; t++) s += colred[t][tid];
        g_cpart[(b * 8 + blockIdx.y) * TQ_ + q0 + tid] = s;
    }
}

// ---------------------------------------------------------------------------
// Kernel 3: out GEMM (tf32 TC), split-K=4 (8 splits measured: out_reduce
// traffic doubles, +5us > gemm gain), in-block column-sum inverse +
// normalize fused into A load.  z = b + 4*s.  grid (2, 8, 16) = 256 blocks.
// ---------------------------------------------------------------------------
__global__ __launch_bounds__(256) void out_gemm_kernel(const float* __restrict__ qin) {
    __shared__ __align__(16) float sinv[128];

    const int b = blockIdx.z & 3;
    const int s = blockIdx.z >> 2;
    const int kbeg = s * 128;
    const int tid = threadIdx.x;

    if (tid < 128) {
        const int qq = kbeg + tid;
        float sum = 0.f;
#pragma unroll
        for (int t = 0; t < 8; t++) sum += g_cpart[(b * 8 + t) * TQ_ + qq];
        sinv[tid] = __fdividef(1.0f, sum);
    }
    __syncthreads();

    float* C = g_part + (size_t)(s * 4 + b) * (TP_ * D_);
    tf32_gemm_64x128<true>(g_sc + (size_t)b * TP_ * TQ_,
                           qin + (size_t)b * TQ_ * D_, C,
                           sinv - kbeg, D_, TQ_,
                           kbeg, kbeg + 128,
                           blockIdx.y * 64, blockIdx.x * 128);
}

// Reduce out partials: out = sum over 4 splits, fixed order.  Deterministic.
__global__ __launch_bounds__(256) void out_reduce_kernel(float* __restrict__ out) {
    const int i = blockIdx.x * 256 + threadIdx.x;  // float4 idx
    constexpr int NB4 = (TP_ * D_) / 4;
    const int b = i / NB4;
    const int j = i % NB4;
    float4 v[4];
#pragma unroll
    for (int s = 0; s < 4; s++)
        v[s] = *((const float4*)g_part + (size_t)(s * 4 + b) * NB4 + j);
    float4 r;
    r.x = (v[0].x + v[1].x) + (v[2].x + v[3].x);
    r.y = (v[0].y + v[1].y) + (v[2].y + v[3].y);
    r.z = (v[0].z + v[1].z) + (v[2].z + v[3].z);
    r.w = (v[0].w + v[1].w) + (v[2].w + v[3].w);
    *((float4*)out + i) = r;
}

// ---------------------------------------------------------------------------
// Launch.  Measured dead ends: multi-stream per-batch pipelining +4us;
// inline dual-partial reads in SINGLE-buffered energy +12us (OK under
// double-buffering); 128x64/BK=16 double-buffered gemm tile +4us; fused
// last-block reduces (threadfence) +7us; out split-K=8 +5us reduce traffic;
// f16x2 tanh 2-pass on MUFU, no gain; energy double-buffer itself neutral.
// ---------------------------------------------------------------------------
extern "C" void kernel_launch(void* const* d_in, const int* in_sizes, int n_in,
                              void* d_out, int out_size) {
    const float* q = (const float*)d_in[0];   // [B,Tq,D]
    const float* p = (const float*)d_in[1];   // [B,Tp,D]
    const float* W0 = (const float*)d_in[2];  // [D,D]
    const float* W1 = (const float*)d_in[3];  // [D,D]
    const float* vc = (const float*)d_in[4];  // [D,1]
    float* out = (float*)d_out;               // [B,Tp,D]

    // 1. Projections (tensor core, split-K=2; partials consumed by energy)
    {
        dim3 grid(D_ / 128, (B_ * TQ_) / 64, 4);
        proj_kernel<<<grid, 256>>>(q, p, W0, W1);
    }
    // 2. Energies -> exp(score) + column partials (inline proj reduce,
    //    double-buffered)
    {
        dim3 grid(TQ_ / 64, TP_ / 64, B_);
        energy_kernel<<<grid, 256>>>(vc);
    }
    // 3. Output GEMM (tensor core, split-K=4, in-block colsum + normalize)
    {
        dim3 grid(D_ / 128, TP_ / 64, 16);
        out_gemm_kernel<<<grid, 256>>>(q);
        out_reduce_kernel<<<(B_ * TP_ * D_ / 4) / 256, 256>>>(out);
    }
}

// round 17
// speedup vs baseline: 1.0199x; 1.0010x over previous
#include <cuda_runtime.h>
#include <cstddef>
#include <cstdint>

// Problem constants
#define B_   4
#define TQ_  512
#define TP_  512
#define D_   256

// ---------------------------------------------------------------------------
// Scratch (static device globals)
// ---------------------------------------------------------------------------
__device__ float g_sc[(size_t)B_ * TP_ * TQ_];   // exp(scores) [B,Tp,Tq]
__device__ float g_cpart[B_ * 8 * TQ_];          // per-p-tile column partials
// Shared split-K partial buffer: proj uses 4 slices of B*TQ*D (8MB);
// out uses 16 slices of TP*D (8MB).  Serial kernels -> safe reuse.
__device__ float g_part[(size_t)16 * B_ * TQ_ * D_ / 4];

// ---------------------------------------------------------------------------
// fp32 HW tanh (1 MUFU op).
// ---------------------------------------------------------------------------
__device__ __forceinline__ float ftanh(float x) {
    float r;
    asm("tanh.approx.f32 %0, %1;" : "=f"(r) : "f"(x));
    return r;
}

__device__ __forceinline__ uint32_t f2tf32(float x) {
    uint32_t r;
    asm("cvt.rna.tf32.f32 %0, %1;" : "=r"(r) : "f"(x));
    return r;
}

// ---------------------------------------------------------------------------
// tf32 tensor-core GEMM slice.  Block tile 64x128, BK=32, single-buffered,
// 256 threads = 8 warps (2m x 4n), warp tile 32x32 (8 MMAs / 16 LDS).
// C[M,N] (partial) = A[M, kbeg:kend] * B[kbeg:kend, N], both row-major.
// If SCALE, A column k is scaled by cs[k] at load (cs may be smem).
// ---------------------------------------------------------------------------
template <bool SCALE>
__device__ __forceinline__ void tf32_gemm_64x128(const float* __restrict__ A,
                                                 const float* __restrict__ B,
                                                 float* __restrict__ C,
                                                 const float* cs,
                                                 int N, int K, int kbeg, int kend,
                                                 int m0, int n0) {
    __shared__ uint32_t As[64][36];   // [m][k]
    __shared__ uint32_t Bs[32][136];  // [k][n]

    const int tid = threadIdx.x;
    const int lane = tid & 31;
    const int w = tid >> 5;
    const int wm = (w >> 2) * 32;   // 0 / 32
    const int wn = (w & 3) * 32;    // 0 / 32 / 64 / 96
    const int frow = lane >> 2;     // 0..7
    const int fcol = lane & 3;      // 0..3

    float c[2][4][4];
#pragma unroll
    for (int mi = 0; mi < 2; mi++)
#pragma unroll
        for (int ni = 0; ni < 4; ni++)
#pragma unroll
            for (int k = 0; k < 4; k++) c[mi][ni][k] = 0.0f;

    float4 ra[2], rb[4];
    auto loadG = [&](int k0) {
#pragma unroll
        for (int s = 0; s < 2; s++) {
            int id = tid + s * 256;
            int r = id >> 3, cc = (id & 7) * 4;
            ra[s] = *(const float4*)&A[(size_t)(m0 + r) * K + k0 + cc];
            if (SCALE) {
                float4 sc = *(const float4*)&cs[k0 + cc];
                ra[s].x *= sc.x; ra[s].y *= sc.y;
                ra[s].z *= sc.z; ra[s].w *= sc.w;
            }
        }
#pragma unroll
        for (int s = 0; s < 4; s++) {
            int id = tid + s * 256;
            int r = id >> 5, cc = (id & 31) * 4;
            rb[s] = *(const float4*)&B[(size_t)(k0 + r) * N + n0 + cc];
        }
    };
    auto storeS = [&]() {
#pragma unroll
        for (int s = 0; s < 2; s++) {
            int id = tid + s * 256;
            int r = id >> 3, cc = (id & 7) * 4;
            As[r][cc + 0] = f2tf32(ra[s].x);
            As[r][cc + 1] = f2tf32(ra[s].y);
            As[r][cc + 2] = f2tf32(ra[s].z);
            As[r][cc + 3] = f2tf32(ra[s].w);
        }
#pragma unroll
        for (int s = 0; s < 4; s++) {
            int id = tid + s * 256;
            int r = id >> 5, cc = (id & 31) * 4;
            Bs[r][cc + 0] = f2tf32(rb[s].x);
            Bs[r][cc + 1] = f2tf32(rb[s].y);
            Bs[r][cc + 2] = f2tf32(rb[s].z);
            Bs[r][cc + 3] = f2tf32(rb[s].w);
        }
    };

    loadG(kbeg);
    for (int k0 = kbeg; k0 < kend; k0 += 32) {
        storeS();
        __syncthreads();
        if (k0 + 32 < kend) loadG(k0 + 32);
#pragma unroll
        for (int ks = 0; ks < 4; ks++) {
            const int kk = ks * 8;
            uint32_t a[2][4], bfr[4][2];
#pragma unroll
            for (int mi = 0; mi < 2; mi++) {
                a[mi][0] = As[wm + mi * 16 + frow][kk + fcol];
                a[mi][1] = As[wm + mi * 16 + frow + 8][kk + fcol];
                a[mi][2] = As[wm + mi * 16 + frow][kk + fcol + 4];
                a[mi][3] = As[wm + mi * 16 + frow + 8][kk + fcol + 4];
            }
#pragma unroll
            for (int ni = 0; ni < 4; ni++) {
                bfr[ni][0] = Bs[kk + fcol][wn + ni * 8 + frow];
                bfr[ni][1] = Bs[kk + fcol + 4][wn + ni * 8 + frow];
            }
#pragma unroll
            for (int mi = 0; mi < 2; mi++)
#pragma unroll
                for (int ni = 0; ni < 4; ni++)
                    asm volatile(
                        "mma.sync.aligned.m16n8k8.row.col.f32.tf32.tf32.f32 "
                        "{%0,%1,%2,%3},{%4,%5,%6,%7},{%8,%9},{%0,%1,%2,%3};"
                        : "+f"(c[mi][ni][0]), "+f"(c[mi][ni][1]),
                          "+f"(c[mi][ni][2]), "+f"(c[mi][ni][3])
                        : "r"(a[mi][0]), "r"(a[mi][1]), "r"(a[mi][2]),
                          "r"(a[mi][3]), "r"(bfr[ni][0]), "r"(bfr[ni][1]));
        }
        __syncthreads();
    }

#pragma unroll
    for (int mi = 0; mi < 2; mi++)
#pragma unroll
        for (int ni = 0; ni < 4; ni++) {
            int rr = m0 + wm + mi * 16 + frow;
            int cc = n0 + wn + ni * 8 + fcol * 2;
            *(float2*)&C[(size_t)rr * N + cc] =
                make_float2(c[mi][ni][0], c[mi][ni][1]);
            *(float2*)&C[(size_t)(rr + 8) * N + cc] =
                make_float2(c[mi][ni][2], c[mi][ni][3]);
        }
}

// ---------------------------------------------------------------------------
// Kernel 1: projections (tf32 TC), split-K=2.  z = t + 2*s.
//   part[s*2+t] = (t?p:q)[:, ks:ks+128] @ (t?W1:W0)[ks:ks+128, :]
// grid (2, 32, 4) = 256 blocks.  NO reduce kernel -- energy sums the two
// split partials inline (hidden under its double-buffered MUFU loop).
// ---------------------------------------------------------------------------
__global__ __launch_bounds__(256) void proj_kernel(const float* __restrict__ q,
                                                   const float* __restrict__ p,
                                                   const float* __restrict__ W0,
                                                   const float* __restrict__ W1) {
    const int t = blockIdx.z & 1;
    const int s = blockIdx.z >> 1;
    const float* A = t ? p : q;
    const float* Bw = t ? W1 : W0;
    float* C = g_part + (size_t)(s * 2 + t) * (B_ * TQ_ * D_);
    tf32_gemm_64x128<false>(A, Bw, C, nullptr, D_, D_,
                            s * 128, s * 128 + 128,
                            blockIdx.y * 64, blockIdx.x * 128);
}

// ---------------------------------------------------------------------------
// Kernel 2: energies -> exp(score) + per-block column partial sums.
// fp32 MUFU.TANH, 64x64 tile, 4x4 micro -- AT the MUFU floor.
// DOUBLE-BUFFERED: chunk k+1's 16 LDG.128 (both proj split partials for pp
// and pq) issue before chunk k's MUFU loop; the partial sum a+b happens in
// storeS afterwards, so the extra loads hide under ~14K cyc of MUFU work.
// ---------------------------------------------------------------------------
__global__ __launch_bounds__(256) void energy_kernel(const float* __restrict__ vc) {
    __shared__ float sp[2][64][33];
    __shared__ float sq[2][64][33];
    __shared__ float sv[256];
    __shared__ float colred[16][64];

    const int b = blockIdx.z;
    const int p0 = blockIdx.y * 64;
    const int q0 = blockIdx.x * 64;
    const int tid = threadIdx.x;
    const int tx = tid & 15;
    const int ty = tid >> 4;

    constexpr size_t NFT = (size_t)B_ * TQ_ * D_;
    // proj slices: t=0 -> pq, t=1 -> pp; split s=0 slices {0,1}, s=1 {2,3}
    const float* pq0 = g_part + 0 * NFT + ((size_t)b * TQ_ + q0) * D_;
    const float* pq1 = g_part + 2 * NFT + ((size_t)b * TQ_ + q0) * D_;
    const float* pp0 = g_part + 1 * NFT + ((size_t)b * TP_ + p0) * D_;
    const float* pp1 = g_part + 3 * NFT + ((size_t)b * TP_ + p0) * D_;

    sv[tid] = vc[tid];

    float4 rPa[2], rPb[2], rQa[2], rQb[2];
    auto loadG = [&](int d0) {
#pragma unroll
        for (int s = 0; s < 2; s++) {
            int id = tid + s * 256;
            int r = id >> 3, cc = (id & 7) * 4;
            size_t off = (size_t)r * D_ + d0 + cc;
            rPa[s] = *(const float4*)&pp0[off];
            rPb[s] = *(const float4*)&pp1[off];
            rQa[s] = *(const float4*)&pq0[off];
            rQb[s] = *(const float4*)&pq1[off];
        }
    };
    auto storeS = [&](int st) {
#pragma unroll
        for (int s = 0; s < 2; s++) {
            int id = tid + s * 256;
            int r = id >> 3, cc = (id & 7) * 4;
            sp[st][r][cc + 0] = rPa[s].x + rPb[s].x;
            sp[st][r][cc + 1] = rPa[s].y + rPb[s].y;
            sp[st][r][cc + 2] = rPa[s].z + rPb[s].z;
            sp[st][r][cc + 3] = rPa[s].w + rPb[s].w;
            sq[st][r][cc + 0] = rQa[s].x + rQb[s].x;
            sq[st][r][cc + 1] = rQa[s].y + rQb[s].y;
            sq[st][r][cc + 2] = rQa[s].z + rQb[s].z;
            sq[st][r][cc + 3] = rQa[s].w + rQb[s].w;
        }
    };

    float acc[4][4];
#pragma unroll
    for (int i = 0; i < 4; i++)
#pragma unroll
        for (int j = 0; j < 4; j++) acc[i][j] = 0.0f;

    loadG(0);
    storeS(0);
    __syncthreads();

#pragma unroll 1
    for (int ch = 0; ch < 8; ch++) {
        if (ch < 7) loadG((ch + 1) * 32);
        const int st = ch & 1;
#pragma unroll 8
        for (int d = 0; d < 32; d++) {
            float v = sv[ch * 32 + d];
            float a[4], bb[4];
#pragma unroll
            for (int i = 0; i < 4; i++) a[i] = sp[st][ty * 4 + i][d];
#pragma unroll
            for (int j = 0; j < 4; j++) bb[j] = sq[st][tx * 4 + j][d];
#pragma unroll
            for (int i = 0; i < 4; i++)
#pragma unroll
                for (int j = 0; j < 4; j++)
                    acc[i][j] = fmaf(v, ftanh(a[i] + bb[j]), acc[i][j]);
        }
        if (ch < 7) storeS((ch + 1) & 1);
        __syncthreads();
    }

    float colp[4] = {0.f, 0.f, 0.f, 0.f};
#pragma unroll
    for (int i = 0; i < 4; i++) {
        float4 o;
        o.x = __expf(acc[i][0]);
        o.y = __expf(acc[i][1]);
        o.z = __expf(acc[i][2]);
        o.w = __expf(acc[i][3]);
        colp[0] += o.x; colp[1] += o.y; colp[2] += o.z; colp[3] += o.w;
        *(float4*)&g_sc[((size_t)b * TP_ + p0 + ty * 4 + i) * TQ_ + q0 + tx * 4] = o;
    }
    *(float4*)&colred[ty][tx * 4] =
        make_float4(colp[0], colp[1], colp[2], colp[3]);
    __syncthreads();
    if (tid < 64) {
        float s = colred[0][tid];
#pragma unroll
        for (int t = 1; t < 16; t++) s += colred[t][tid];
        g_cpart[(b * 8 + blockIdx.y) * TQ_ + q0 + tid] = s;
    }
}

// ---------------------------------------------------------------------------
// Kernel 3: out GEMM (tf32 TC), split-K=4, in-block column-sum inverse +
// normalize fused into A load.  z = b + 4*s.  grid (2, 8, 16) = 256 blocks.
// ---------------------------------------------------------------------------
__global__ __launch_bounds__(256) void out_gemm_kernel(const float* __restrict__ qin) {
    __shared__ __align__(16) float sinv[128];

    const int b = blockIdx.z & 3;
    const int s = blockIdx.z >> 2;
    const int kbeg = s * 128;
    const int tid = threadIdx.x;

    if (tid < 128) {
        const int qq = kbeg + tid;
        float sum = 0.f;
#pragma unroll
        for (int t = 0; t < 8; t++) sum += g_cpart[(b * 8 + t) * TQ_ + qq];
        sinv[tid] = __fdividef(1.0f, sum);
    }
    __syncthreads();

    float* C = g_part + (size_t)(s * 4 + b) * (TP_ * D_);
    tf32_gemm_64x128<true>(g_sc + (size_t)b * TP_ * TQ_,
                           qin + (size_t)b * TQ_ * D_, C,
                           sinv - kbeg, D_, TQ_,
                           kbeg, kbeg + 128,
                           blockIdx.y * 64, blockIdx.x * 128);
}

// ---------------------------------------------------------------------------
// Reduce out partials: out = sum over 4 splits, fixed order.  Deterministic.
// 4 outputs/thread, all 16 loads issued before any adds (MLP=16/thread --
// the partials come from DRAM after L2 eviction, so deep MLP is the lever;
// measured at 1 out/thread: 5.9us, issue=4.7%, DRAM-latency-bound).
// grid 128 x 256.
// ---------------------------------------------------------------------------
__global__ __launch_bounds__(256) void out_reduce_kernel(float* __restrict__ out) {
    constexpr int NB4 = (TP_ * D_) / 4;  // 32768 float4 per batch
    const int base = blockIdx.x * 1024 + threadIdx.x;  // 4 outs, stride 256

    float4 v[4][4];
#pragma unroll
    for (int u = 0; u < 4; u++) {
        const int i = base + u * 256;
        const int b = i / NB4;
        const int j = i % NB4;
#pragma unroll
        for (int s = 0; s < 4; s++)
            v[u][s] = *((const float4*)g_part + (size_t)(s * 4 + b) * NB4 + j);
    }
#pragma unroll
    for (int u = 0; u < 4; u++) {
        float4 r;
        r.x = (v[u][0].x + v[u][1].x) + (v[u][2].x + v[u][3].x);
        r.y = (v[u][0].y + v[u][1].y) + (v[u][2].y + v[u][3].y);
        r.z = (v[u][0].z + v[u][1].z) + (v[u][2].z + v[u][3].z);
        r.w = (v[u][0].w + v[u][1].w) + (v[u][2].w + v[u][3].w);
        *((float4*)out + base + u * 256) = r;
    }
}

// ---------------------------------------------------------------------------
// Launch.  Measured dead ends: multi-stream per-batch pipelining +4us;
// inline dual-partial reads in SINGLE-buffered energy +12us (OK under
// double-buffering); 128x64/BK=16 double-buffered gemm tile +4us; fused
// last-block reduces (threadfence) +7us; out split-K=8 +5us reduce traffic;
// f16x2 tanh 2-pass on MUFU, no gain.
// ---------------------------------------------------------------------------
extern "C" void kernel_launch(void* const* d_in, const int* in_sizes, int n_in,
                              void* d_out, int out_size) {
    const float* q = (const float*)d_in[0];   // [B,Tq,D]
    const float* p = (const float*)d_in[1];   // [B,Tp,D]
    const float* W0 = (const float*)d_in[2];  // [D,D]
    const float* W1 = (const float*)d_in[3];  // [D,D]
    const float* vc = (const float*)d_in[4];  // [D,1]
    float* out = (float*)d_out;               // [B,Tp,D]

    // 1. Projections (tensor core, split-K=2; partials consumed by energy)
    {
        dim3 grid(D_ / 128, (B_ * TQ_) / 64, 4);
        proj_kernel<<<grid, 256>>>(q, p, W0, W1);
    }
    // 2. Energies -> exp(score) + column partials (inline proj reduce,
    //    double-buffered)
    {
        dim3 grid(TQ_ / 64, TP_ / 64, B_);
        energy_kernel<<<grid, 256>>>(vc);
    }
    // 3. Output GEMM (tensor core, split-K=4, in-block colsum + normalize)
    {
        dim3 grid(D_ / 128, TP_ / 64, 16);
        out_gemm_kernel<<<grid, 256>>>(q);
        out_reduce_kernel<<<(B_ * TP_ * D_ / 4) / 1024, 256>>>(out);
    }
}